// round 16
// baseline (speedup 1.0000x reference)
#include <cuda_runtime.h>
#include <cuda_bf16.h>
#include <math.h>
#include <stdint.h>

#define NB   2048
#define NT   60
#define NDL  100
#define ND   512
#define NH   256

// ---------------- scratch (device globals) ----------------
__device__ float g_h0[NB * ND];
__device__ float g_stats[2 * ND];
__device__ float g_gates[2][NB * 3 * NH];          // x@Wih^T + bih (fp32)
__device__ __nv_bfloat16 g_xh[NB * ND];            // BN+lrelu x split hi
__device__ __nv_bfloat16 g_xl[NB * ND];            // BN+lrelu x split lo
__device__ __nv_bfloat16 g_whh[2][3 * NH * NH];    // Whh split hi
__device__ __nv_bfloat16 g_whl[2][3 * NH * NH];    // Whh split lo
__device__ __nv_bfloat16 g_wihh[2][3 * NH * ND];   // Wih split hi
__device__ __nv_bfloat16 g_wihl[2][3 * NH * ND];   // Wih split lo
__device__ __nv_bfloat16 g_w1h[NH * 2 * NH];       // attn_W1 split hi
__device__ __nv_bfloat16 g_w1l[NH * 2 * NH];       // attn_W1 split lo
__device__ __nv_bfloat16 g_gruh[NB * NT * 2 * NH]; // gru out bf16 hi (= state)
__device__ __nv_bfloat16 g_grul[NB * NT * 2 * NH]; // gru out bf16 lo
__device__ float g_s[NB * NT];
__device__ float g_p1[NB * NT * 8];                // per-(b,t) joint dots row.jW
__device__ int   g_sync[2 * 16 * NT];              // group flags [dir][mtile][t]

__device__ __forceinline__ void bsplit(float v, __nv_bfloat16& h, __nv_bfloat16& l) {
    h = __float2bfloat16(v);
    l = __float2bfloat16(v - __bfloat162float(h));
}

__device__ __forceinline__ void mma16816(float& d0, float& d1, float& d2, float& d3,
    uint32_t a0, uint32_t a1, uint32_t a2, uint32_t a3, uint32_t b0, uint32_t b1)
{
    asm volatile("mma.sync.aligned.m16n8k16.row.col.f32.bf16.bf16.f32 "
                 "{%0,%1,%2,%3},{%4,%5,%6,%7},{%8,%9},{%0,%1,%2,%3};"
                 : "+f"(d0), "+f"(d1), "+f"(d2), "+f"(d3)
                 : "r"(a0), "r"(a1), "r"(a2), "r"(a3), "r"(b0), "r"(b1));
}

#define LDSM4(r0, r1, r2, r3, addr) \
    asm volatile("ldmatrix.sync.aligned.m8n8.x4.shared.b16 {%0,%1,%2,%3}, [%4];" \
                 : "=r"(r0), "=r"(r1), "=r"(r2), "=r"(r3) : "r"(addr))

__device__ __forceinline__ void cpasync16(void* sdst, const void* gsrc) {
    uint32_t s = (uint32_t)__cvta_generic_to_shared(sdst);
    asm volatile("cp.async.cg.shared.global [%0], [%1], 16;" :: "r"(s), "l"(gsrc));
}
#define CP_COMMIT() asm volatile("cp.async.commit_group;")
#define CP_WAIT0()  asm volatile("cp.async.wait_group 0;")
#define CP_WAIT1()  asm volatile("cp.async.wait_group 1;")

__device__ __forceinline__ float ftanh_hw(float x) {
    float r;
    asm("tanh.approx.f32 %0, %1;" : "=f"(r) : "f"(x));
    return r;
}
__device__ __forceinline__ float fsig_hw(float x) {
    return fmaf(ftanh_hw(0.5f * x), 0.5f, 0.5f);
}
__device__ __forceinline__ float b2f(__nv_bfloat16 v) { return __bfloat162float(v); }

// swizzled smem index (elements): stride 64, XOR 8-col blocks by (row&7).
__device__ __forceinline__ int swzidx(int r, int c) {
    return r * 64 + ((((c >> 3) ^ (r & 7)) << 3) | (c & 7));
}

// ---------------- fused fc GEMM + weight splits + flag reset ---------------------
__global__ void __launch_bounds__(256) fc_prep(
    const float* __restrict__ z, const float* __restrict__ W_fc,
    const float* __restrict__ b_fc,
    const float* __restrict__ Whh_f, const float* __restrict__ Whh_b,
    const float* __restrict__ Wih_f, const float* __restrict__ Wih_b,
    const float* __restrict__ W1)
{
    __shared__ float As[16][65];
    __shared__ float Bs[16][65];
    if (blockIdx.x < 256) {
        const int N = ND, K = NDL;
        int tid = threadIdx.x;
        int tx = tid & 15, ty = tid >> 4;
        int m0 = (blockIdx.x >> 3) * 64, n0 = (blockIdx.x & 7) * 64;
        float acc[4][4] = {};
        for (int k0 = 0; k0 < K; k0 += 16) {
            #pragma unroll
            for (int i = 0; i < 4; i++) {
                int lin = tid + i * 256;
                int m = lin >> 4, k = lin & 15;
                As[k][m] = (k0 + k < K) ? z[(m0 + m) * K + k0 + k] : 0.f;
            }
            #pragma unroll
            for (int i = 0; i < 4; i++) {
                int lin = tid + i * 256;
                int n = lin >> 4, k = lin & 15;
                Bs[k][n] = (k0 + k < K) ? W_fc[(n0 + n) * K + k0 + k] : 0.f;
            }
            __syncthreads();
            #pragma unroll
            for (int kk = 0; kk < 16; kk++) {
                float a[4], b[4];
                #pragma unroll
                for (int i = 0; i < 4; i++) a[i] = As[kk][ty * 4 + i];
                #pragma unroll
                for (int j = 0; j < 4; j++) b[j] = Bs[kk][tx * 4 + j];
                #pragma unroll
                for (int i = 0; i < 4; i++)
                    #pragma unroll
                    for (int j = 0; j < 4; j++) acc[i][j] += a[i] * b[j];
            }
            __syncthreads();
        }
        #pragma unroll
        for (int i = 0; i < 4; i++) {
            int m = m0 + ty * 4 + i;
            #pragma unroll
            for (int j = 0; j < 4; j++) {
                int n = n0 + tx * 4 + j;
                g_h0[m * N + n] = acc[i][j] + b_fc[n];
            }
        }
    } else {
        int i = (blockIdx.x - 256) * 256 + threadIdx.x;
        bsplit(Wih_f[i], g_wihh[0][i], g_wihl[0][i]);
        bsplit(Wih_b[i], g_wihh[1][i], g_wihl[1][i]);
        if (i < 3 * NH * NH) {
            bsplit(Whh_f[i], g_whh[0][i], g_whl[0][i]);
            bsplit(Whh_b[i], g_whh[1][i], g_whl[1][i]);
        }
        if (i < NH * 2 * NH) bsplit(W1[i], g_w1h[i], g_w1l[i]);
        if (i < 2 * 16 * NT) g_sync[i] = 0;
    }
}

// ---------------- batchnorm stats -------------------------------------------------
__global__ void __launch_bounds__(256) bn_stats()
{
    int c = blockIdx.x;
    float s = 0.f, s2 = 0.f;
    for (int r = threadIdx.x; r < NB; r += 256) {
        float v = g_h0[r * ND + c];
        s += v; s2 += v * v;
    }
    __shared__ float sh[256], sh2[256];
    sh[threadIdx.x] = s; sh2[threadIdx.x] = s2;
    __syncthreads();
    for (int o = 128; o > 0; o >>= 1) {
        if (threadIdx.x < o) {
            sh[threadIdx.x]  += sh[threadIdx.x + o];
            sh2[threadIdx.x] += sh2[threadIdx.x + o];
        }
        __syncthreads();
    }
    if (threadIdx.x == 0) {
        float mu = sh[0] / (float)NB;
        g_stats[c] = mu;
        g_stats[ND + c] = sh2[0] / (float)NB - mu * mu;
    }
}

// ---------------- BN + LeakyReLU + bf16 hi/lo split -------------------------------
__global__ void __launch_bounds__(256) bn_apply_split(
    const float* __restrict__ bn_g, const float* __restrict__ bn_b)
{
    int i = blockIdx.x * 256 + threadIdx.x;
    int c = i & (ND - 1);
    float mu = g_stats[c], var = g_stats[ND + c];
    float v = (g_h0[i] - mu) * rsqrtf(var + 1e-5f) * bn_g[c] + bn_b[c];
    v = (v >= 0.f) ? v : 0.2f * v;
    bsplit(v, g_xh[i], g_xl[i]);
}

// ---------------- LDSM fragment loaders ------------------------------------------
__device__ __forceinline__ void ldsm_afrags(
    uint32_t As_u32, uint32_t afr[4][4], int wm, int lane, int kk)
{
    const int g = lane >> 3, lr = lane & 7;
    const int scol = kk * 2 + (g >> 1);
    #pragma unroll
    for (int mt = 0; mt < 4; mt++) {
        const int row = wm * 64 + mt * 16 + ((g & 1) << 3) + lr;
        const uint32_t addr = As_u32 + row * 128 + ((scol ^ (row & 7)) << 4);
        LDSM4(afr[mt][0], afr[mt][1], afr[mt][2], afr[mt][3], addr);
    }
}

__device__ __forceinline__ void ldsmB8(
    uint32_t base, uint32_t bfr[8][2], int wj, int lane, int kk)
{
    const int g = lane >> 3, lr = lane & 7;
    const int scol = kk * 2 + (g & 1);
    #pragma unroll
    for (int q = 0; q < 4; q++) {
        const int nt = 2 * q + (g >> 1);
        const int row = wj * 64 + nt * 8 + lr;
        const uint32_t addr = base + row * 128 + ((scol ^ (row & 7)) << 4);
        LDSM4(bfr[2 * q][0], bfr[2 * q][1], bfr[2 * q + 1][0], bfr[2 * q + 1][1], addr);
    }
}

__device__ __forceinline__ void mma48(
    const uint32_t afr[4][4], const uint32_t bfr[8][2], float acc[4][8][4])
{
    #pragma unroll
    for (int mt = 0; mt < 4; mt++)
        #pragma unroll
        for (int nt = 0; nt < 8; nt++)
            mma16816(acc[mt][nt][0], acc[mt][nt][1], acc[mt][nt][2], acc[mt][nt][3],
                     afr[mt][0], afr[mt][1], afr[mt][2], afr[mt][3],
                     bfr[nt][0], bfr[nt][1]);
}

// ---------------- double-buffered 128x256 x K=512 split-MMA ----------------------
// stage layout (elems): As0[8192] As1[8192] Bs0[16384] Bs1[16384] = 49152
#define ST3 49152
#define SM3_BYTES (2 * ST3 * 2)     // 196608

// 3-term: Ah@(Bh+Bl) + Al@Bh (gate GEMM)
__device__ __forceinline__ void split_mma_128x256(
    const __nv_bfloat16* __restrict__ ah, const __nv_bfloat16* __restrict__ al,
    const __nv_bfloat16* __restrict__ bh, const __nv_bfloat16* __restrict__ bl,
    __nv_bfloat16* smem, float acc[4][8][4], int tid)
{
    const uint32_t s_u32 = (uint32_t)__cvta_generic_to_shared(smem);
    const int warp = tid >> 5, lane = tid & 31;
    const int wm = warp >> 2, wj = warp & 3;

#define LOAD3(STG, KS) {                                                          \
    __nv_bfloat16* sb = smem + (STG) * ST3;                                       \
    _Pragma("unroll")                                                             \
    for (int i = 0; i < 4; i++) {                                                 \
        int u = tid + 256 * i;                                                    \
        int r = u >> 3, c = (u & 7) << 3;                                         \
        cpasync16(&sb[swzidx(r, c)],        &ah[(size_t)r * 512 + (KS) + c]);     \
        cpasync16(&sb[8192 + swzidx(r, c)], &al[(size_t)r * 512 + (KS) + c]);     \
    }                                                                             \
    _Pragma("unroll")                                                             \
    for (int i = 0; i < 8; i++) {                                                 \
        int u = tid + 256 * i;                                                    \
        int r = u >> 3, c = (u & 7) << 3;                                         \
        cpasync16(&sb[16384 + swzidx(r, c)], &bh[(size_t)r * 512 + (KS) + c]);    \
        cpasync16(&sb[32768 + swzidx(r, c)], &bl[(size_t)r * 512 + (KS) + c]);    \
    }                                                                             \
    CP_COMMIT(); }

    LOAD3(0, 0);
    for (int ksi = 0; ksi < 8; ksi++) {
        if (ksi > 0) __syncthreads();
        if (ksi < 7) { LOAD3((ksi + 1) & 1, (ksi + 1) * 64); }
        if (ksi < 7) { CP_WAIT1(); } else { CP_WAIT0(); }
        __syncthreads();
        const uint32_t sb = s_u32 + ((ksi & 1) * ST3) * 2;
        const uint32_t As0 = sb, As1 = sb + 8192 * 2;
        const uint32_t Bs0 = sb + 16384 * 2, Bs1 = sb + 32768 * 2;
        #pragma unroll
        for (int kk = 0; kk < 4; kk++) {
            uint32_t afr[4][4], bfr[8][2];
            ldsm_afrags(As0, afr, wm, lane, kk);
            ldsmB8(Bs1, bfr, wj, lane, kk);
            mma48(afr, bfr, acc);
            ldsmB8(Bs0, bfr, wj, lane, kk);
            mma48(afr, bfr, acc);
            ldsm_afrags(As1, afr, wm, lane, kk);
            mma48(afr, bfr, acc);
        }
    }
}

// ---------------- gate GEMM on tensor cores (128x256 tiles, 3-term) --------------
__global__ void __launch_bounds__(256) gemm_gates_mma(
    const float* __restrict__ bf, const float* __restrict__ bb)
{
    extern __shared__ __nv_bfloat16 dynsm[];
    const int tid = threadIdx.x;
    const int ct = blockIdx.x;
    const int m0 = blockIdx.y * 128;
    const int dir = blockIdx.z;
    const float* bias = dir ? bb : bf;
    float* C = g_gates[dir];

    float acc[4][8][4];
    #pragma unroll
    for (int a = 0; a < 4; a++)
        #pragma unroll
        for (int b = 0; b < 8; b++)
            #pragma unroll
            for (int q = 0; q < 4; q++) acc[a][b][q] = 0.f;

    split_mma_128x256(g_xh + (size_t)m0 * 512, g_xl + (size_t)m0 * 512,
                      g_wihh[dir] + (size_t)ct * 256 * 512,
                      g_wihl[dir] + (size_t)ct * 256 * 512,
                      dynsm, acc, tid);

    const int warp = tid >> 5, lane = tid & 31;
    const int wm = warp >> 2, wj = warp & 3;
    const int gID = lane >> 2, tig = lane & 3;
    #pragma unroll
    for (int mt = 0; mt < 4; mt++)
        #pragma unroll
        for (int part = 0; part < 2; part++) {
            const int m = m0 + wm * 64 + mt * 16 + gID + part * 8;
            #pragma unroll
            for (int nt = 0; nt < 8; nt++)
                #pragma unroll
                for (int cc = 0; cc < 2; cc++) {
                    const int n = ct * 256 + wj * 64 + nt * 8 + tig * 2 + cc;
                    C[(size_t)m * 768 + n] = acc[mt][nt][part * 2 + cc] + bias[n];
                }
        }
}

// ---------------- attention + fused joint dots -----------------------------------
// MMA: 2-term (Ah@(Bh+Bl)). Also computes exact p1[m] = (hi+lo row).jW per row.
__global__ void __launch_bounds__(256) attn_mma(
    const float* __restrict__ b1, const float* __restrict__ W2,
    const float* __restrict__ jW)
{
    extern __shared__ __nv_bfloat16 dynsm[];
    __shared__ float jWs[6][512];
    __shared__ float red[128];
    __shared__ float p1s[256][6];

    const int tid = threadIdx.x;
    const int m0 = blockIdx.x * 128;
    for (int i = tid; i < 6 * 512; i += 256) jWs[i >> 9][i & 511] = jW[i];
    if (tid < 128) red[tid] = 0.f;

    float acc[4][8][4];
    #pragma unroll
    for (int a = 0; a < 4; a++)
        #pragma unroll
        for (int b = 0; b < 8; b++)
            #pragma unroll
            for (int q = 0; q < 4; q++) acc[a][b][q] = 0.f;
    float p1a[6];
    #pragma unroll
    for (int j = 0; j < 6; j++) p1a[j] = 0.f;

    const uint32_t s_u32 = (uint32_t)__cvta_generic_to_shared(dynsm);
    const int warp = tid >> 5, lane = tid & 31;
    const int wm = warp >> 2, wj = warp & 3;
    const int prow = tid & 127;            // p1 pass: row
    const int pcolb = (tid >> 7) * 32;     // p1 pass: col half

    const __nv_bfloat16* __restrict__ ah = g_gruh + (size_t)m0 * 512;
    const __nv_bfloat16* __restrict__ al = g_grul + (size_t)m0 * 512;
    const __nv_bfloat16* __restrict__ bh = g_w1h;
    const __nv_bfloat16* __restrict__ bl = g_w1l;

#define ALOAD3(STG, KS) {                                                         \
    __nv_bfloat16* sb = dynsm + (STG) * ST3;                                      \
    _Pragma("unroll")                                                             \
    for (int i = 0; i < 4; i++) {                                                 \
        int u = tid + 256 * i;                                                    \
        int r = u >> 3, c = (u & 7) << 3;                                         \
        cpasync16(&sb[swzidx(r, c)],        &ah[(size_t)r * 512 + (KS) + c]);     \
        cpasync16(&sb[8192 + swzidx(r, c)], &al[(size_t)r * 512 + (KS) + c]);     \
    }                                                                             \
    _Pragma("unroll")                                                             \
    for (int i = 0; i < 8; i++) {                                                 \
        int u = tid + 256 * i;                                                    \
        int r = u >> 3, c = (u & 7) << 3;                                         \
        cpasync16(&sb[16384 + swzidx(r, c)], &bh[(size_t)r * 512 + (KS) + c]);    \
        cpasync16(&sb[32768 + swzidx(r, c)], &bl[(size_t)r * 512 + (KS) + c]);    \
    }                                                                             \
    CP_COMMIT(); }

    ALOAD3(0, 0);
    for (int ksi = 0; ksi < 8; ksi++) {
        if (ksi > 0) __syncthreads();
        if (ksi < 7) { ALOAD3((ksi + 1) & 1, (ksi + 1) * 64); }
        if (ksi < 7) { CP_WAIT1(); } else { CP_WAIT0(); }
        __syncthreads();
        const uint32_t sb = s_u32 + ((ksi & 1) * ST3) * 2;
        const uint32_t As0 = sb;
        const uint32_t Bs0 = sb + 16384 * 2, Bs1 = sb + 32768 * 2;
        #pragma unroll
        for (int kk = 0; kk < 4; kk++) {
            uint32_t afr[4][4], bfr[8][2];
            ldsm_afrags(As0, afr, wm, lane, kk);
            ldsmB8(Bs1, bfr, wj, lane, kk);
            mma48(afr, bfr, acc);
            ldsmB8(Bs0, bfr, wj, lane, kk);
            mma48(afr, bfr, acc);
        }
        // p1 pass: exact (hi+lo) row dot jW for this 64-col slab
        {
            const __nv_bfloat16* stq = dynsm + (ksi & 1) * ST3;
            const int ks = ksi * 64;
            #pragma unroll
            for (int q = 0; q < 4; q++) {
                const int cb = pcolb + q * 8;
                const int off = swzidx(prow, cb);
                uint4 vh = *(const uint4*)&stq[off];
                uint4 vl = *(const uint4*)&stq[8192 + off];
                const __nv_bfloat16* ph = (const __nv_bfloat16*)&vh;
                const __nv_bfloat16* pl = (const __nv_bfloat16*)&vl;
                #pragma unroll
                for (int e = 0; e < 8; e++) {
                    float x = b2f(ph[e]) + b2f(pl[e]);
                    const int col = ks + cb + e;
                    #pragma unroll
                    for (int j = 0; j < 6; j++) p1a[j] += x * jWs[j][col];
                }
            }
        }
    }
#undef ALOAD3

    #pragma unroll
    for (int j = 0; j < 6; j++) p1s[tid][j] = p1a[j];

    const int gID = lane >> 2, tig = lane & 3;
    __syncthreads();
    #pragma unroll
    for (int mt = 0; mt < 4; mt++)
        #pragma unroll
        for (int part = 0; part < 2; part++) {
            float s = 0.f;
            #pragma unroll
            for (int nt = 0; nt < 8; nt++)
                #pragma unroll
                for (int cc = 0; cc < 2; cc++) {
                    int n = wj * 64 + nt * 8 + tig * 2 + cc;
                    s += ftanh_hw(acc[mt][nt][part * 2 + cc] + b1[n]) * W2[n];
                }
            s += __shfl_xor_sync(0xffffffffu, s, 1);
            s += __shfl_xor_sync(0xffffffffu, s, 2);
            if (tig == 0)
                atomicAdd(&red[wm * 64 + mt * 16 + gID + part * 8], s);
        }
    __syncthreads();
    if (tid < 128) {
        g_s[m0 + tid] = red[tid];
        #pragma unroll
        for (int j = 0; j < 6; j++)
            g_p1[(size_t)(m0 + tid) * 8 + j] = p1s[tid][j] + p1s[tid + 128][j];
    }
}

// ---------------- GRU LDSM inner blocks ------------------------------------------
__device__ __forceinline__ void ldsm_bfrags(
    uint32_t Bs_u32, uint32_t bfr[6][2], int wj, int lane, int kk)
{
    const int g = lane >> 3, lr = lane & 7;
    const int scol = kk * 2 + (g & 1);
    #pragma unroll
    for (int q = 0; q < 3; q++) {
        const int nt = 2 * q + (g >> 1);
        const int row = (nt >> 1) * 64 + wj * 16 + (nt & 1) * 8 + lr;
        const uint32_t addr = Bs_u32 + row * 128 + ((scol ^ (row & 7)) << 4);
        LDSM4(bfr[2 * q][0], bfr[2 * q][1], bfr[2 * q + 1][0], bfr[2 * q + 1][1], addr);
    }
}

__device__ __forceinline__ void mma_all(
    const uint32_t afr[4][4], const uint32_t bfr[6][2], float acc[4][6][4])
{
    #pragma unroll
    for (int mt = 0; mt < 4; mt++)
        #pragma unroll
        for (int nt = 0; nt < 6; nt++)
            mma16816(acc[mt][nt][0], acc[mt][nt][1], acc[mt][nt][2], acc[mt][nt][3],
                     afr[mt][0], afr[mt][1], afr[mt][2], afr[mt][3],
                     bfr[nt][0], bfr[nt][1]);
}

__device__ __forceinline__ void mma_block2(
    uint32_t As_u32, uint32_t Bs1_u32, uint32_t Bs2_u32,
    float acc[4][6][4], int wm, int wj, int lane)
{
    #pragma unroll
    for (int kk = 0; kk < 4; kk++) {
        uint32_t afr[4][4], bfr[6][2];
        ldsm_afrags(As_u32, afr, wm, lane, kk);
        ldsm_bfrags(Bs1_u32, bfr, wj, lane, kk);
        mma_all(afr, bfr, acc);
        ldsm_bfrags(Bs2_u32, bfr, wj, lane, kk);
        mma_all(afr, bfr, acc);
    }
}

__device__ __forceinline__ void mma_block1(
    uint32_t As_u32, uint32_t Bs_u32,
    float acc[4][6][4], int wm, int wj, int lane)
{
    #pragma unroll
    for (int kk = 0; kk < 4; kk++) {
        uint32_t afr[4][4], bfr[6][2];
        ldsm_afrags(As_u32, afr, wm, lane, kk);
        ldsm_bfrags(Bs_u32, bfr, wj, lane, kk);
        mma_all(afr, bfr, acc);
    }
}

// ---------------- persistent GRU (unchanged) -------------------------------------
#define SLAB (192 * 64)
#define ATILE (128 * 64)
__global__ void __launch_bounds__(256) gru_persist(
    const float* __restrict__ bhh_f, const float* __restrict__ bhh_b)
{
    extern __shared__ __nv_bfloat16 smem[];
    __nv_bfloat16* Bsh = smem;
    __nv_bfloat16* Bsl = smem + 4 * SLAB;
    __nv_bfloat16* A0  = smem + 8 * SLAB;
    __nv_bfloat16* A1  = A0 + ATILE;
    const uint32_t Bsh_u32 = (uint32_t)__cvta_generic_to_shared(Bsh);
    const uint32_t Bsl_u32 = (uint32_t)__cvta_generic_to_shared(Bsl);
    const uint32_t A0_u32  = (uint32_t)__cvta_generic_to_shared(A0);
    const uint32_t A1_u32  = (uint32_t)__cvta_generic_to_shared(A1);
    const uint32_t SLAB_B  = SLAB * 2;

    const int bid = blockIdx.x;
    const int dir = bid >> 6;
    const int sub = bid & 63;
    const int j0 = (sub & 3) * 64;
    const int jslab = j0 >> 6;
    const int mtile = sub >> 2;
    const int m0 = mtile * 128;
    int* const flag = &g_sync[(dir * 16 + mtile) * NT];

    const float* bhh = dir ? bhh_b : bhh_f;
    const float* gin = g_gates[dir];
    const __nv_bfloat16* __restrict__ wh = g_whh[dir];
    const __nv_bfloat16* __restrict__ wl = g_whl[dir];

    const int tid = threadIdx.x;
    const int warp = tid >> 5, lane = tid & 31;
    const int wm = warp >> 2, wj = warp & 3;
    const int gID = lane >> 2, tig = lane & 3;

    int lr[4], lc[4];
    #pragma unroll
    for (int i = 0; i < 4; i++) {
        int u = tid + 256 * i;
        lr[i] = u >> 3; lc[i] = (u & 7) * 8;
    }

    #pragma unroll
    for (int i = 0; i < 24; i++) {
        int u = tid + 256 * i;
        int r = u >> 5;
        int c = (u & 31) * 8;
        int slab = c >> 6, cs = c & 63;
        int g = r >> 6, j = j0 + (r & 63);
        *(uint4*)&Bsh[slab * SLAB + swzidx(r, cs)] =
            *(const uint4*)&wh[(g * NH + j) * NH + c];
        *(uint4*)&Bsl[slab * SLAB + swzidx(r, cs)] =
            *(const uint4*)&wl[(g * NH + j) * NH + c];
    }
    __syncthreads();

    for (int t = 0; t < NT; t++) {
        const int tt  = dir ? (NT - 1 - t) : t;
        const int ttp = dir ? (NT - t) : (t - 1);

        float acc[4][6][4];
        #pragma unroll
        for (int a = 0; a < 4; a++)
            #pragma unroll
            for (int b = 0; b < 6; b++)
                #pragma unroll
                for (int q = 0; q < 4; q++) acc[a][b][q] = 0.f;

        if (t > 0) {
            if (tid == 0) {
                while (*(volatile int*)&flag[t - 1] < 4) { }
                __threadfence();
            }
            __syncthreads();

            const int ks0 = (((jslab + 1) & 3)) * 64;
            #pragma unroll
            for (int i = 0; i < 4; i++)
                cpasync16(&A0[swzidx(lr[i], lc[i])],
                          &g_gruh[((size_t)(m0 + lr[i]) * NT + ttp) * 512 + dir * NH + ks0 + lc[i]]);
            CP_COMMIT();
            for (int it = 0; it < 4; it++) {
                const int ksl = (jslab + 1 + it) & 3;
                const int ks = ksl * 64;
                CP_WAIT0(); __syncthreads();
                #pragma unroll
                for (int i = 0; i < 4; i++)
                    cpasync16(&A1[swzidx(lr[i], lc[i])],
                              &g_grul[((size_t)(m0 + lr[i]) * NT + ttp) * 512 + dir * NH + ks + lc[i]]);
                CP_COMMIT();
                mma_block2(A0_u32, Bsl_u32 + ksl * SLAB_B, Bsh_u32 + ksl * SLAB_B,
                           acc, wm, wj, lane);
                CP_WAIT0(); __syncthreads();
                if (it < 3) {
                    const int ksn = ((jslab + 2 + it) & 3) * 64;
                    #pragma unroll
                    for (int i = 0; i < 4; i++)
                        cpasync16(&A0[swzidx(lr[i], lc[i])],
                                  &g_gruh[((size_t)(m0 + lr[i]) * NT + ttp) * 512 + dir * NH + ksn + lc[i]]);
                    CP_COMMIT();
                }
                mma_block1(A1_u32, Bsh_u32 + ksl * SLAB_B, acc, wm, wj, lane);
            }
        }

        #pragma unroll
        for (int mt = 0; mt < 4; mt++)
            #pragma unroll
            for (int part = 0; part < 2; part++) {
                const int m = m0 + wm * 64 + mt * 16 + gID + part * 8;
                const int mrow = m - m0;
                #pragma unroll
                for (int jn = 0; jn < 2; jn++) {
                    const int jg = j0 + wj * 16 + jn * 8 + tig * 2;
                    float hn2[2];
                    #pragma unroll
                    for (int cc = 0; cc < 2; cc++) {
                        const int j = jg + cc;
                        float ghr = acc[mt][jn][part * 2 + cc]     + bhh[j];
                        float ghz = acc[mt][2 + jn][part * 2 + cc] + bhh[NH + j];
                        float ghn = acc[mt][4 + jn][part * 2 + cc] + bhh[2 * NH + j];
                        const float* gp = gin + m * 3 * NH + j;
                        float r  = fsig_hw(gp[0] + ghr);
                        float zz = fsig_hw(gp[NH] + ghz);
                        float nn = ftanh_hw(gp[2 * NH] + r * ghn);
                        float hold = 0.f;
                        if (t > 0) {
                            const int sw = swzidx(mrow, j & 63);
                            hold = b2f(A0[sw]) + b2f(A1[sw]);
                        }
                        hn2[cc] = (1.f - zz) * nn + zz * hold;
                    }
                    __nv_bfloat16 h0, l0, h1, l1;
                    bsplit(hn2[0], h0, l0);
                    bsplit(hn2[1], h1, l1);
                    __nv_bfloat162 vh, vl;
                    vh.x = h0; vh.y = h1; vl.x = l0; vl.y = l1;
                    size_t go = ((size_t)m * NT + tt) * 512 + dir * NH + jg;
                    *(__nv_bfloat162*)(g_gruh + go) = vh;
                    *(__nv_bfloat162*)(g_grul + go) = vl;
                }
            }

        if (t < NT - 1) {
            __syncthreads();
            if (tid == 0) {
                __threadfence();
                atomicAdd(&flag[t], 1);
            }
        }
    }
}

// ---------------- tiny tail: softmax + cJ + FK (no gru reads) --------------------
__global__ void __launch_bounds__(64) ctx_fk(
    const float* __restrict__ jb, float* __restrict__ out)
{
    const int b = blockIdx.x;
    const int tid = threadIdx.x;
    __shared__ float w[NT];
    __shared__ float cJ[6];
    if (tid < 6) cJ[tid] = 0.f;
    if (tid == 0) {
        float mx = -1e30f;
        float tmpv[NT];
        for (int t = 0; t < NT; t++) {
            tmpv[t] = g_s[b * NT + t];
            if (tmpv[t] > mx) mx = tmpv[t];
        }
        float s = 0.f;
        for (int t = 0; t < NT; t++) { tmpv[t] = __expf(tmpv[t] - mx); s += tmpv[t]; }
        float inv = __fdividef(1.f, s);
        for (int t = 0; t < NT; t++) w[t] = tmpv[t] * inv;
    }
    __syncthreads();

    float pj[6];
    if (tid < NT) {
        const float* p1 = &g_p1[(size_t)(b * NT + tid) * 8];
        #pragma unroll
        for (int j = 0; j < 6; j++) {
            pj[j] = p1[j];
            atomicAdd(&cJ[j], w[tid] * pj[j]);
        }
    }
    __syncthreads();

    if (tid < NT) {
        const float LO[6] = {-3.1416f, -1.5708f, -3.1416f, -2.6f, -1.5708f, -1.2f};
        const float UP[6] = { 3.1416f,  1.5708f,  3.1416f,  0.1f,  1.5708f,  1.2f};
        float th[6];
        #pragma unroll
        for (int j = 0; j < 6; j++)
            th[j] = (pj[j] + cJ[j] + jb[j]) * (UP[j] - LO[j]) + LO[j];

        float c0[3] = {1.f, 0.f, 0.f}, c1[3] = {0.f, 1.f, 0.f}, c2[3] = {0.f, 0.f, 1.f};
        float px = 0.f, py = 0.f, pz = 0.10f;
        const float sh2x = 0.f, sh2y = 0.f, sh2z = 0.10f;

        float c, s, tmp;
        c = cosf(th[0]); s = sinf(th[0]);
        #pragma unroll
        for (int i = 0; i < 3; i++) { tmp = c*c0[i] + s*c1[i]; c1[i] = c*c1[i] - s*c0[i]; c0[i] = tmp; }
        c = cosf(th[1]); s = sinf(th[1]);
        #pragma unroll
        for (int i = 0; i < 3; i++) { tmp = c*c1[i] + s*c2[i]; c2[i] = c*c2[i] - s*c1[i]; c1[i] = tmp; }
        c = cosf(th[2]); s = sinf(th[2]);
        #pragma unroll
        for (int i = 0; i < 3; i++) { tmp = c*c0[i] - s*c2[i]; c2[i] = c*c2[i] + s*c0[i]; c0[i] = tmp; }
        px -= 0.25f * c1[0]; py -= 0.25f * c1[1]; pz -= 0.25f * c1[2];
        float fax = px, fay = py, faz = pz;
        c = cosf(th[3]); s = sinf(th[3]);
        #pragma unroll
        for (int i = 0; i < 3; i++) { tmp = c*c1[i] + s*c2[i]; c2[i] = c*c2[i] - s*c1[i]; c1[i] = tmp; }
        c = cosf(th[4]); s = sinf(th[4]);
        #pragma unroll
        for (int i = 0; i < 3; i++) { tmp = c*c0[i] - s*c2[i]; c2[i] = c*c2[i] + s*c0[i]; c0[i] = tmp; }
        px -= 0.25f * c1[0]; py -= 0.25f * c1[1]; pz -= 0.25f * c1[2];
        float wx = px, wy = py, wz = pz;
        c = cosf(th[5]); s = sinf(th[5]);
        #pragma unroll
        for (int i = 0; i < 3; i++) { tmp = c*c1[i] + s*c2[i]; c2[i] = c*c2[i] - s*c1[i]; c1[i] = tmp; }

        float f1x = wx - 0.08f*c1[0] + 0.02f*c2[0];
        float f1y = wy - 0.08f*c1[1] + 0.02f*c2[1];
        float f1z = wz - 0.08f*c1[2] + 0.02f*c2[2];
        float f4x = wx - 0.08f*c1[0] - 0.02f*c2[0];
        float f4y = wy - 0.08f*c1[1] - 0.02f*c2[1];
        float f4z = wz - 0.08f*c1[2] - 0.02f*c2[2];

        float d1x = sh2x - fax, d1y = sh2y - fay, d1z = sh2z - faz;
        float d2x = wx - fax,   d2y = wy - fay,   d2z = wz - faz;
        float bodyL = 0.5f * (sqrtf(d1x*d1x + d1y*d1y + d1z*d1z)
                            + sqrtf(d2x*d2x + d2y*d2y + d2z*d2z));
        float inv = 1.f / bodyL;

        float* o = out + ((size_t)b * NT + tid) * 9;
        o[0] = (wx  - sh2x) * inv; o[1] = (wy  - sh2y) * inv; o[2] = (wz  - sh2z) * inv;
        o[3] = (f1x - sh2x) * inv; o[4] = (f1y - sh2y) * inv; o[5] = (f1z - sh2z) * inv;
        o[6] = (f4x - sh2x) * inv; o[7] = (f4y - sh2y) * inv; o[8] = (f4z - sh2z) * inv;
    }
}

// ---------------- host launcher ---------------------------------------------------
extern "C" void kernel_launch(void* const* d_in, const int* in_sizes, int n_in,
                              void* d_out, int out_size)
{
    const float* z       = (const float*)d_in[0];
    const float* W_fc    = (const float*)d_in[1];
    const float* b_fc    = (const float*)d_in[2];
    const float* bn_g    = (const float*)d_in[3];
    const float* bn_b    = (const float*)d_in[4];
    const float* Wih_f   = (const float*)d_in[5];
    const float* Whh_f   = (const float*)d_in[6];
    const float* bih_f   = (const float*)d_in[7];
    const float* bhh_f   = (const float*)d_in[8];
    const float* Wih_b   = (const float*)d_in[9];
    const float* Whh_b   = (const float*)d_in[10];
    const float* bih_b   = (const float*)d_in[11];
    const float* bhh_b   = (const float*)d_in[12];
    const float* attn_W1 = (const float*)d_in[13];
    const float* attn_b1 = (const float*)d_in[14];
    const float* attn_W2 = (const float*)d_in[15];
    const float* joint_W = (const float*)d_in[16];
    const float* joint_b = (const float*)d_in[17];
    float* out = (float*)d_out;

    static int smem_set = 0;
    const int gru_smem = (8 * SLAB + 2 * ATILE) * 2;
    if (!smem_set) {
        cudaFuncSetAttribute(gru_persist,
            cudaFuncAttributeMaxDynamicSharedMemorySize, gru_smem);
        cudaFuncSetAttribute(attn_mma,
            cudaFuncAttributeMaxDynamicSharedMemorySize, SM3_BYTES);
        cudaFuncSetAttribute(gemm_gates_mma,
            cudaFuncAttributeMaxDynamicSharedMemorySize, SM3_BYTES);
        smem_set = 1;
    }

    // 1) fc GEMM + weight splits + flag reset
    fc_prep<<<1792, 256>>>(z, W_fc, b_fc, Whh_f, Whh_b, Wih_f, Wih_b, attn_W1);
    // 2) batch stats
    bn_stats<<<ND, 256>>>();
    // 3) BN + lrelu + bf16 split of x
    bn_apply_split<<<NB * ND / 256, 256>>>(bn_g, bn_b);
    // 4) gate GEMM on tensor cores
    gemm_gates_mma<<<dim3(3, NB / 128, 2), 256, SM3_BYTES>>>(bih_f, bih_b);
    // 5) GRU recurrence (persistent)
    gru_persist<<<128, 256, gru_smem>>>(bhh_f, bhh_b);
    // 6) attention scores + fused joint dots (single pass over gru rows)
    attn_mma<<<NB * NT / 128, 256, SM3_BYTES>>>(attn_b1, attn_W2, joint_W);
    // 7) tiny tail: softmax + cJ + FK
    ctx_fk<<<NB, 64>>>(joint_b, out);
}